// round 5
// baseline (speedup 1.0000x reference)
#include <cuda_runtime.h>
#include <mma.h>
#include <math.h>
#include <cstdint>

using namespace nvcuda;

#define Bb 16
#define Cc 64
#define Hh 256
#define Ww 256
#define MM 16
#define SS 32

// ---------------- scratch ----------------------------------------------------
__device__ float2 d_tw[256];
__device__ float  d_TA[32*256];          // forward trig  (cos, -sin) tf32-RNA
__device__ float  d_TE[32*256];          // inverse trig  (cos, +sin) tf32-RNA
__device__ float2 d_Xw[Bb*Cc*Hh*MM];
__device__ float2 d_Xf[Bb*Cc*SS*MM];
__device__ float2 d_Y [Bb*Cc*SS*MM];
__device__ float2 d_Z [Bb*Hh*Cc*MM];
__device__ float2 d_wt[2*256*4096];
__device__ float  d_V [(size_t)Bb*Cc*Hh*Ww];   // pre-GELU scratch (256MB)
__device__ float  d_partS[512*128];
__device__ float  d_partQ[512*128];
__device__ float2 d_stat[Bb*32];

__device__ __forceinline__ uint32_t f2tf32(float f) {
    uint32_t r; asm("cvt.rna.tf32.f32 %0, %1;" : "=r"(r) : "f"(f)); return r;
}
__device__ __forceinline__ uint32_t smem_u32(const void* p) {
    uint32_t a;
    asm("{ .reg .u64 t; cvta.to.shared.u64 t, %1; cvt.u32.u64 %0, t; }" : "=r"(a) : "l"(p));
    return a;
}
__device__ __forceinline__ void cp16(uint32_t dst, const void* src) {
    asm volatile("cp.async.ca.shared.global [%0], [%1], 16;" :: "r"(dst), "l"(src));
}
#define CP_COMMIT()  asm volatile("cp.async.commit_group;" ::: "memory")
#define CP_WAIT(n)   asm volatile("cp.async.wait_group %0;" :: "n"(n) : "memory")

// ---------------- init: twiddles + tf32 trig tables ----------------------------
__global__ void k_init() {
    int t = threadIdx.x;
    float s, c;
    sincospif((float)t * (1.0f / 128.0f), &s, &c);
    d_tw[t] = make_float2(c, s);
#pragma unroll
    for (int kk = 0; kk < 32; kk++) {
        int ky = kk >> 1;
        float s2, c2;
        sincospif((float)((ky * t) & 255) * (1.0f / 128.0f), &s2, &c2);
        d_TA[kk * 256 + t] = __uint_as_float(f2tf32((kk & 1) ? -s2 : c2));
        d_TE[kk * 256 + t] = __uint_as_float(f2tf32((kk & 1) ?  s2 : c2));
    }
}

// ---------------- weight transpose --------------------------------------------
__global__ void k_transpose_w(const float* __restrict__ w1r, const float* __restrict__ w1i,
                              const float* __restrict__ w2r, const float* __restrict__ w2i) {
    int n = blockIdx.x * 256 + threadIdx.x;
    int half = n >> 20;
    int rem  = n & ((1 << 20) - 1);
    int mode = rem >> 12;
    int io   = rem & 4095;
    int kx = mode >> 4, ky = mode & 15;
    int i = io >> 6, o = io & 63;
    int src = ((i * 64 + o) * 16 + kx) * 16 + ky;
    const float* wr = half ? w2r : w1r;
    const float* wi = half ? w2i : w1i;
    d_wt[n] = make_float2(wr[src], wi[src]);
}

// ---------------- stage A: DFT over W via tf32 wmma ------------------------------
#define DW_SMEM 172544
__global__ void __launch_bounds__(256, 1)
k_dftW_tc(const float* __restrict__ x) {
    extern __shared__ float sm[];
    uint32_t sb = smem_u32(sm);
    int bc = blockIdx.x, t = threadIdx.x;
    int wid = t >> 5;
    float* sA = sm + 32768;              // [32][256] row-major
    float* sC = sm + 40960;              // [32][68]
    const float* xblk = x + (size_t)bc * 65536;

#pragma unroll
    for (int c = 0; c < 2; c++) {
#pragma unroll
        for (int j = 0; j < 16; j++) {
            int u = j * 256 + t;
            int hl = u >> 6, wu = u & 63;
            cp16(sb + c * 65536 + u * 16,
                 xblk + (size_t)(c * 64 + hl) * 256 + wu * 4);
        }
        CP_COMMIT();
    }
    for (int idx = t; idx < 8192; idx += 256) sA[idx] = d_TA[idx];

    int m0 = (wid >> 2) * 16;
    int n0 = (wid & 3) * 16;

#pragma unroll
    for (int c = 0; c < 4; c++) {
        if (c < 3) { CP_WAIT(1); } else { CP_WAIT(0); }
        __syncthreads();
        float* xb = sm + (c & 1) * 16384;
        wmma::fragment<wmma::accumulator, 16, 16, 8, float> acc;
        wmma::fill_fragment(acc, 0.0f);
#pragma unroll
        for (int k0 = 0; k0 < 32; k0++) {
            wmma::fragment<wmma::matrix_a, 16, 16, 8, wmma::precision::tf32, wmma::row_major> af;
            wmma::fragment<wmma::matrix_b, 16, 16, 8, wmma::precision::tf32, wmma::col_major> bf;
            wmma::load_matrix_sync(af, sA + m0 * 256 + k0 * 8, 256);
            wmma::load_matrix_sync(bf, xb + n0 * 256 + k0 * 8, 256);
            wmma::mma_sync(acc, af, bf, acc);
        }
        __syncthreads();
        if (c + 2 < 4) {
#pragma unroll
            for (int j = 0; j < 16; j++) {
                int u = j * 256 + t;
                int hl = u >> 6, wu = u & 63;
                cp16(sb + (c & 1) * 65536 + u * 16,
                     xblk + (size_t)((c + 2) * 64 + hl) * 256 + wu * 4);
            }
            CP_COMMIT();
        }
        wmma::store_matrix_sync(sC + m0 * 68 + n0, acc, 68, wmma::mem_row_major);
        __syncthreads();
#pragma unroll
        for (int r = 0; r < 4; r++) {
            int idx = r * 256 + t;
            int ky = idx & 15, hl = idx >> 4;
            float re = sC[(2 * ky) * 68 + hl];
            float im = sC[(2 * ky + 1) * 68 + hl];
            d_Xw[((bc << 8) + c * 64 + hl) * 16 + ky] = make_float2(re, im);
        }
        __syncthreads();
    }
}

// ---------------- stage B: DFT over H (scalar) -----------------------------------
__global__ void k_dftH() {
    int bc = blockIdx.x;
    __shared__ float2 sX[4096];
    __shared__ float2 stw[256];
    if (threadIdx.x < 256) stw[threadIdx.x] = d_tw[threadIdx.x];
    for (int idx = threadIdx.x; idx < 4096; idx += 256)
        sX[idx] = d_Xw[bc * 4096 + idx];
    __syncthreads();
#pragma unroll
    for (int rep = 0; rep < 2; rep++) {
        int m = threadIdx.x + rep * 256;
        int kxi = m >> 4, ky = m & 15;
        int kx = (kxi < 16) ? kxi : (224 + kxi);
        float re = 0.f, im = 0.f;
        int ang = 0;
#pragma unroll 8
        for (int h = 0; h < 256; h++) {
            float2 tv = stw[ang];
            ang = (ang + kx) & 255;
            float2 xv = sX[h * 16 + ky];
            re = fmaf(xv.x, tv.x, re); re = fmaf(xv.y,  tv.y, re);
            im = fmaf(xv.y, tv.x, im); im = fmaf(-xv.x, tv.y, im);
        }
        d_Xf[(bc * 32 + kxi) * 16 + ky] = make_float2(re, im);
    }
}

// ---------------- stage C: per-mode channel mix -----------------------------------
__global__ void k_specmul() {
    int m = blockIdx.x;
    int half = m >> 8, kx = (m >> 4) & 15, ky = m & 15;
    int kxi = half * 16 + kx;
    __shared__ float2 sX[1024];
    __shared__ float2 sW[4096];
    for (int idx = threadIdx.x; idx < 1024; idx += 256) {
        int bv = idx >> 6, i = idx & 63;
        sX[idx] = d_Xf[((bv * 64 + i) * 32 + kxi) * 16 + ky];
    }
    for (int idx = threadIdx.x; idx < 4096; idx += 256)
        sW[idx] = d_wt[(size_t)m * 4096 + idx];
    __syncthreads();
#pragma unroll
    for (int k = 0; k < 4; k++) {
        int p = threadIdx.x + k * 256;
        int bv = p >> 6, o = p & 63;
        float re = 0.f, im = 0.f;
#pragma unroll 16
        for (int i = 0; i < 64; i++) {
            float2 xv = sX[bv * 64 + i];
            float2 wv = sW[i * 64 + o];
            re = fmaf(xv.x, wv.x, re); re = fmaf(-xv.y, wv.y, re);
            im = fmaf(xv.x, wv.y, im); im = fmaf( xv.y, wv.x, im);
        }
        d_Y[((bv * 64 + o) * 32 + kxi) * 16 + ky] = make_float2(re, im);
    }
}

// ---------------- stage D: inverse DFT over H --------------------------------------
__global__ void k_idftH() {
    int bc = blockIdx.x;
    int b = bc >> 6, o = bc & 63;
    __shared__ float2 sY[512];
    __shared__ float2 stw[256];
    if (threadIdx.x < 256) stw[threadIdx.x] = d_tw[threadIdx.x];
    for (int idx = threadIdx.x; idx < 512; idx += 256)
        sY[idx] = d_Y[bc * 512 + idx];
    __syncthreads();
    int h = threadIdx.x;
    float ar[16], ai[16];
#pragma unroll
    for (int ky = 0; ky < 16; ky++) { ar[ky] = 0.f; ai[ky] = 0.f; }
#pragma unroll
    for (int kxi = 0; kxi < 32; kxi++) {
        int kx = (kxi < 16) ? kxi : (224 + kxi);
        float2 tv = stw[(kx * h) & 255];
#pragma unroll
        for (int ky = 0; ky < 16; ky++) {
            float2 y = sY[kxi * 16 + ky];
            ar[ky] = fmaf(y.x, tv.x, ar[ky]); ar[ky] = fmaf(-y.y, tv.y, ar[ky]);
            ai[ky] = fmaf(y.x, tv.y, ai[ky]); ai[ky] = fmaf( y.y, tv.x, ai[ky]);
        }
    }
#pragma unroll
    for (int ky = 0; ky < 16; ky++) {
        float sc = (ky ? 2.0f : 1.0f) * (1.0f / 65536.0f);
        d_Z[((b * 256 + h) * 64 + o) * 16 + ky] = make_float2(ar[ky] * sc, ai[ky] * sc);
    }
}

// ---------------- stage E1: GEMM-only, writes pre-GELU v --------------------------
// Per (b, h, wh): C[w=128][o=64] = sum_k A[k][w]*B[k][o], K=96, then
// v = C + bias + x  (exact fp32 residual), streamed to d_V.
// smem floats: A bufs 2x[32][132] @0  (C^T [64][132] overlays),
//              B [96][66] @8448, bias @14784. total 14848 f = 59392 B.
#define LDA3 132
#define LDB3 66
#define LDCT 132
#define E1_SMEM 59392

__global__ void __launch_bounds__(256, 3)
k_gemmE(const float* __restrict__ x, const float* __restrict__ cw,
        const float* __restrict__ cb) {
    extern __shared__ float sm[];
    uint32_t sb = smem_u32(sm);
    float* fB  = sm + 8448;
    float* sCB = sm + 14784;

    int gx = blockIdx.x;
    int h = gx >> 1, wh = gx & 1;
    int b = blockIdx.y, t = threadIdx.x;
    int wid = t >> 5;

    const float* xbase = x + (size_t)b * 4194304 + (size_t)h * 256 + wh * 128;

    // A chunks 0,1: x channels 0..31, 32..63 (cp.async.ca -> L1 warm for residual)
#pragma unroll
    for (int c = 0; c < 2; c++) {
#pragma unroll
        for (int j = 0; j < 4; j++) {
            int u = j * 256 + t;
            int il = u >> 5, w4 = u & 31;
            cp16(sb + (c * 4224 + il * LDA3 + w4 * 4) * 4,
                 xbase + (size_t)(c * 32 + il) * 65536 + w4 * 4);
        }
        CP_COMMIT();
    }

    // B: conv weights + Z rows (RNA tf32), bias
    for (int idx = t; idx < 4096; idx += 256) {
        int o = idx >> 6, i = idx & 63;
        fB[i * LDB3 + o] = __uint_as_float(f2tf32(cw[idx]));
    }
    for (int idx = t; idx < 1024; idx += 256) {
        float2 z = d_Z[(size_t)(b * 256 + h) * 1024 + idx];
        int o = idx >> 4, ky = idx & 15;
        fB[(64 + 2 * ky) * LDB3 + o] = __uint_as_float(f2tf32(z.x));
        fB[(65 + 2 * ky) * LDB3 + o] = __uint_as_float(f2tf32(-z.y));
    }
    if (t < 64) sCB[t] = cb[t];

    wmma::fragment<wmma::accumulator, 16, 16, 8, float> acc[4];
#pragma unroll
    for (int n0 = 0; n0 < 4; n0++) wmma::fill_fragment(acc[n0], 0.0f);
    int m0 = wid * 16;

    // chunk 0
    CP_WAIT(1);
    __syncthreads();
#pragma unroll
    for (int j = 0; j < 4; j++) {
        wmma::fragment<wmma::matrix_a, 16, 16, 8, wmma::precision::tf32, wmma::col_major> af;
        wmma::load_matrix_sync(af, sm + j * 8 * LDA3 + m0, LDA3);
#pragma unroll
        for (int n0 = 0; n0 < 4; n0++) {
            wmma::fragment<wmma::matrix_b, 16, 16, 8, wmma::precision::tf32, wmma::row_major> bf;
            wmma::load_matrix_sync(bf, fB + j * 8 * LDB3 + n0 * 16, LDB3);
            wmma::mma_sync(acc[n0], af, bf, acc[n0]);
        }
    }
    __syncthreads();
    // chunk 2 (trig) into buf0
#pragma unroll
    for (int j = 0; j < 4; j++) {
        int u = j * 256 + t;
        int kk = u >> 5, w4 = u & 31;
        cp16(sb + (kk * LDA3 + w4 * 4) * 4,
             d_TE + kk * 256 + wh * 128 + w4 * 4);
    }
    CP_COMMIT();

    // chunk 1
    CP_WAIT(1);
    __syncthreads();
#pragma unroll
    for (int j = 0; j < 4; j++) {
        wmma::fragment<wmma::matrix_a, 16, 16, 8, wmma::precision::tf32, wmma::col_major> af;
        wmma::load_matrix_sync(af, sm + 4224 + j * 8 * LDA3 + m0, LDA3);
#pragma unroll
        for (int n0 = 0; n0 < 4; n0++) {
            wmma::fragment<wmma::matrix_b, 16, 16, 8, wmma::precision::tf32, wmma::row_major> bf;
            wmma::load_matrix_sync(bf, fB + (32 + j * 8) * LDB3 + n0 * 16, LDB3);
            wmma::mma_sync(acc[n0], af, bf, acc[n0]);
        }
    }

    // chunk 2
    CP_WAIT(0);
    __syncthreads();
#pragma unroll
    for (int j = 0; j < 4; j++) {
        wmma::fragment<wmma::matrix_a, 16, 16, 8, wmma::precision::tf32, wmma::col_major> af;
        wmma::load_matrix_sync(af, sm + j * 8 * LDA3 + m0, LDA3);
#pragma unroll
        for (int n0 = 0; n0 < 4; n0++) {
            wmma::fragment<wmma::matrix_b, 16, 16, 8, wmma::precision::tf32, wmma::row_major> bf;
            wmma::load_matrix_sync(bf, fB + (64 + j * 8) * LDB3 + n0 * 16, LDB3);
            wmma::mma_sync(acc[n0], af, bf, acc[n0]);
        }
    }
    __syncthreads();                     // A reads done; C^T overlays A
    float* sCT = sm;                     // [o=64][w=128], ld=132
#pragma unroll
    for (int n0 = 0; n0 < 4; n0++)
        wmma::store_matrix_sync(sCT + (n0 * 16) * LDCT + m0, acc[n0], LDCT, wmma::mem_col_major);
    __syncthreads();

    // epilogue: thread owns (o = t>>2, 32 w), fully coalesced float4
    int o = t >> 2, q = t & 3;
    float bias = sCB[o];
    const float* xr = xbase + (size_t)o * 65536;
    float* vr = d_V + (size_t)b * 4194304 + (size_t)o * 65536 + (size_t)h * 256 + wh * 128;
#pragma unroll
    for (int j = 0; j < 8; j++) {
        int wl = q * 32 + j * 4;
        float4 c4 = *(float4*)&sCT[o * LDCT + wl];
        float4 x4 = *(const float4*)&xr[wl];
        c4.x += bias + x4.x; c4.y += bias + x4.y;
        c4.z += bias + x4.z; c4.w += bias + x4.w;
        *(float4*)&vr[wl] = c4;
    }
}

// ---------------- stage E2: streaming GELU + partials ------------------------------
__global__ void k_gelu(float* __restrict__ out) {
    int idx = blockIdx.x * 256 + threadIdx.x;    // one float4
    int t = threadIdx.x;
    int e = idx << 2;
    int b = e >> 22;
    int c = (e >> 16) & 63;
    __shared__ float rs[8], rq[8];
    float4 v = *(float4*)&d_V[(size_t)idx * 4];
    float g0 = 0.5f * v.x * (1.0f + erff(v.x * 0.70710678118654752f));
    float g1 = 0.5f * v.y * (1.0f + erff(v.y * 0.70710678118654752f));
    float g2 = 0.5f * v.z * (1.0f + erff(v.z * 0.70710678118654752f));
    float g3 = 0.5f * v.w * (1.0f + erff(v.w * 0.70710678118654752f));
    float4 g = make_float4(g0, g1, g2, g3);
    *(float4*)&out[(size_t)idx * 4] = g;
    float S = g0 + g1 + g2 + g3;
    float Q = g0 * g0 + g1 * g1 + g2 * g2 + g3 * g3;
#pragma unroll
    for (int off = 16; off > 0; off >>= 1) {
        S += __shfl_xor_sync(0xffffffffu, S, off);
        Q += __shfl_xor_sync(0xffffffffu, Q, off);
    }
    if ((t & 31) == 0) { rs[t >> 5] = S; rq[t >> 5] = Q; }
    __syncthreads();
    if (t == 0) {
        float s = 0.f, q = 0.f;
#pragma unroll
        for (int k = 0; k < 8; k++) { s += rs[k]; q += rq[k]; }
        int bg = b * 32 + (c >> 1);
        int slot = ((c & 1) << 6) + ((e >> 10) & 63);
        d_partS[bg * 128 + slot] = s;
        d_partQ[bg * 128 + slot] = q;
    }
}

// ---------------- stage R: group statistics ------------------------------------------
__global__ void k_stats3() {
    int bg = blockIdx.x;                 // 512 = (b,g)
    int t = threadIdx.x;                 // 128 partials
    __shared__ float rs[4], rq[4];
    float S = d_partS[bg * 128 + t];
    float Q = d_partQ[bg * 128 + t];
#pragma unroll
    for (int off = 16; off > 0; off >>= 1) {
        S += __shfl_xor_sync(0xffffffffu, S, off);
        Q += __shfl_xor_sync(0xffffffffu, Q, off);
    }
    if ((t & 31) == 0) { rs[t >> 5] = S; rq[t >> 5] = Q; }
    __syncthreads();
    if (t == 0) {
        float s = rs[0] + rs[1] + rs[2] + rs[3];
        float q = rq[0] + rq[1] + rq[2] + rq[3];
        const float invN = 1.0f / 131072.0f;
        float mean = s * invN;
        float var  = q * invN - mean * mean;
        d_stat[bg] = make_float2(mean, 1.0f / sqrtf(var + 1e-5f));
    }
}

// ---------------- stage N: normalize ---------------------------------------------------
__global__ void k_norm(const float* __restrict__ gnw, const float* __restrict__ gnb,
                       float* __restrict__ out) {
    int idx = blockIdx.x * 256 + threadIdx.x;
    int e = idx << 2;
    int b = e >> 22;
    int c = (e >> 16) & 63;
    float2 st = d_stat[b * 32 + (c >> 1)];
    float sc = st.y * gnw[c];
    float sh = gnb[c] - st.x * sc;
    float4* o4 = (float4*)out;
    float4 v = o4[idx];
    v.x = fmaf(v.x, sc, sh); v.y = fmaf(v.y, sc, sh);
    v.z = fmaf(v.z, sc, sh); v.w = fmaf(v.w, sc, sh);
    o4[idx] = v;
}

// ---------------- launch -----------------------------------------------------------------
extern "C" void kernel_launch(void* const* d_in, const int* in_sizes, int n_in,
                              void* d_out, int out_size) {
    const float* x    = (const float*)d_in[0];
    const float* w1r  = (const float*)d_in[1];
    const float* w1i  = (const float*)d_in[2];
    const float* w2r  = (const float*)d_in[3];
    const float* w2i  = (const float*)d_in[4];
    const float* cw   = (const float*)d_in[5];
    const float* cb   = (const float*)d_in[6];
    const float* gnw  = (const float*)d_in[7];
    const float* gnb  = (const float*)d_in[8];
    float* out = (float*)d_out;

    cudaFuncSetAttribute(k_dftW_tc, cudaFuncAttributeMaxDynamicSharedMemorySize, DW_SMEM);
    cudaFuncSetAttribute(k_gemmE,  cudaFuncAttributeMaxDynamicSharedMemorySize, E1_SMEM);

    k_init<<<1, 256>>>();
    k_transpose_w<<<8192, 256>>>(w1r, w1i, w2r, w2i);
    k_dftW_tc<<<1024, 256, DW_SMEM>>>(x);
    k_dftH<<<1024, 256>>>();
    k_specmul<<<512, 256>>>();
    k_idftH<<<1024, 256>>>();
    k_gemmE<<<dim3(512, 16), 256, E1_SMEM>>>(x, cw, cb);
    k_gelu<<<65536, 256>>>(out);
    k_stats3<<<512, 128>>>();
    k_norm<<<65536, 256>>>(gnw, gnb, out);
}